// round 16
// baseline (speedup 1.0000x reference)
#include <cuda_runtime.h>
#include <cuda_fp16.h>
#include <math.h>
#include <cstdint>

#define B_   2
#define S_   2048
#define H_   16
#define DK_  64
#define DM_  1024
#define M_   (B_ * S_)   // 4096

// ---------------------------------------------------------------------------
// PTX helpers — sm_80+ portable (harness PTX target is sm_103 WITHOUT 'a';
// tcgen05/TMEM unavailable; mma.sync/ldmatrix/cp.async are the path).
// ---------------------------------------------------------------------------
__device__ __forceinline__ uint32_t smem_u32(const void* p) {
    uint32_t a;
    asm("{ .reg .u64 t; cvta.to.shared.u64 t, %1; cvt.u32.u64 %0, t; }" : "=r"(a) : "l"(p));
    return a;
}
#define CP_ASYNC16(dst, src) \
    asm volatile("cp.async.cg.shared.global [%0], [%1], 16;" :: "r"(dst), "l"(src))
#define CP_COMMIT() asm volatile("cp.async.commit_group;" ::: "memory")
#define CP_WAIT(n)  asm volatile("cp.async.wait_group %0;" :: "n"(n) : "memory")

#define LDSM_X4(r0, r1, r2, r3, addr) \
    asm volatile("ldmatrix.sync.aligned.m8n8.x4.shared.b16 {%0,%1,%2,%3}, [%4];" \
                 : "=r"(r0), "=r"(r1), "=r"(r2), "=r"(r3) : "r"(addr))

#define LDSM_X4_T(r0, r1, r2, r3, addr) \
    asm volatile("ldmatrix.sync.aligned.m8n8.x4.trans.shared.b16 {%0,%1,%2,%3}, [%4];" \
                 : "=r"(r0), "=r"(r1), "=r"(r2), "=r"(r3) : "r"(addr))

#define MMA_F16(c, a, b) \
    asm volatile("mma.sync.aligned.m16n8k16.row.col.f32.f16.f16.f32 " \
                 "{%0,%1,%2,%3}, {%4,%5,%6,%7}, {%8,%9}, {%0,%1,%2,%3};" \
                 : "+f"((c)[0]), "+f"((c)[1]), "+f"((c)[2]), "+f"((c)[3]) \
                 : "r"((a)[0]), "r"((a)[1]), "r"((a)[2]), "r"((a)[3]), \
                   "r"((b)[0]), "r"((b)[1]))

__device__ __forceinline__ uint32_t sw128(uint32_t off) { return off ^ ((off >> 3) & 0x70); }

__device__ __forceinline__ uint32_t pack2h(float x, float y) {
    __half2 h2 = __halves2half2(__float2half(x), __float2half(y));
    return *reinterpret_cast<uint32_t*>(&h2);
}
__device__ __forceinline__ float ex2f(float x) {
    float r;
    asm("ex2.approx.f32 %0, %1;" : "=f"(r) : "f"(x));
    return r;
}
__device__ __forceinline__ uint32_t ex2h2(__half2 x) {
    uint32_t xi = *reinterpret_cast<uint32_t*>(&x), r;
    asm("ex2.approx.f16x2 %0, %1;" : "=r"(r) : "r"(xi));
    return r;
}

// Q prescale: 1/sqrt(64) * log2(e)  (softmax runs in log2 domain)
#define QSCALE 0.18033688011112042f

// ---------------------------------------------------------------------------
// Scratch (device globals)
// ---------------------------------------------------------------------------
__device__ __half g_Ahi[3][(size_t)M_ * DM_];    // A operands (0 reused for attn out)
__device__ __half g_Whi[4][(size_t)DM_ * DM_];   // W^T [N,K] K-contig
__device__ __half g_Q16[B_ * H_ * S_ * DK_];     // [B,H,S,64], pre-scaled by QSCALE
__device__ __half g_K16[B_ * H_ * S_ * DK_];
__device__ __half g_V16[B_ * H_ * S_ * DK_];

// ---------------------------------------------------------------------------
// fp32 -> fp16
// ---------------------------------------------------------------------------
__global__ void __launch_bounds__(256) conv_inputs(const float4* __restrict__ s0,
                                                   const float4* __restrict__ s1,
                                                   const float4* __restrict__ s2)
{
    const int which = blockIdx.y;
    const float4* src = (which == 0) ? s0 : (which == 1) ? s1 : s2;
    uint32_t* hi = reinterpret_cast<uint32_t*>(g_Ahi[which]);
    int i = blockIdx.x * 256 + threadIdx.x;
    float4 v = src[i];
    hi[2 * i + 0] = pack2h(v.x, v.y);
    hi[2 * i + 1] = pack2h(v.z, v.w);
}

// ---------------------------------------------------------------------------
// All 4 weights: W [K,N] fp32 -> transposed fp16 Wt[N,K]
// ---------------------------------------------------------------------------
__global__ void __launch_bounds__(256) conv_weights(const float* __restrict__ W0,
                                                    const float* __restrict__ W1,
                                                    const float* __restrict__ W2,
                                                    const float* __restrict__ W3)
{
    __shared__ float tile[32][33];
    const int which = blockIdx.z;
    const float* W = (which == 0) ? W0 : (which == 1) ? W1 : (which == 2) ? W2 : W3;
    __half* hi = g_Whi[which];
    const int bx = blockIdx.x, by = blockIdx.y;
    const int tx = threadIdx.x, ty = threadIdx.y;     // 32 x 8
    #pragma unroll
    for (int j = 0; j < 32; j += 8)
        tile[ty + j][tx] = W[(size_t)(by * 32 + ty + j) * DM_ + bx * 32 + tx];
    __syncthreads();
    #pragma unroll
    for (int j = 0; j < 32; j += 8)
        hi[(size_t)(bx * 32 + ty + j) * DM_ + by * 32 + tx] = __float2half(tile[tx][ty + j]);
}

// ---------------------------------------------------------------------------
// Single-pass HMMA GEMM core: 64x128 CTA tile, 128 threads (2Mx2N warps,
// warp tile 32x64), BK=64, 2-stage cp.async, 4 CTAs/SM. (unchanged)
// ---------------------------------------------------------------------------
#define GM 64
#define GN 128
#define GSTAGE 24576
#define GEMM_SMEM (2 * GSTAGE)

__device__ __forceinline__ void gemm_core(const __half* __restrict__ A,
                                          const __half* __restrict__ W,
                                          const float* __restrict__ bias,
                                          float* __restrict__ Cext,
                                          __half* __restrict__ D16,
                                          float oscale, int mode, char* smem)
{
    const uint32_t sb = smem_u32(smem);
    const int t = threadIdx.x, lane = t & 31, wid = t >> 5;
    const int warpM = wid >> 1, warpN = wid & 1;
    const int row0 = blockIdx.y * GM, col0 = blockIdx.x * GN;

    float c[2][8][4] = {};

    auto issue = [&](int i) {
        const int kc = i * 64;
        const uint32_t ab = sb + (uint32_t)(i & 1) * GSTAGE;
        const uint32_t bb = ab + 8192u;
        #pragma unroll
        for (int j = 0; j < 4; j++) {
            int g = t + j * 128, r = g >> 3, ccol = (g & 7) * 8;
            uint32_t so = sw128((uint32_t)(r * 128 + ccol * 2));
            CP_ASYNC16(ab + so, A + (size_t)(row0 + r) * DM_ + kc + ccol);
        }
        #pragma unroll
        for (int j = 0; j < 8; j++) {
            int g = t + j * 128, r = g >> 3, ccol = (g & 7) * 8;
            uint32_t so = sw128((uint32_t)(r * 128 + ccol * 2));
            CP_ASYNC16(bb + so, W + (size_t)(col0 + r) * DM_ + kc + ccol);
        }
    };

    issue(0);
    CP_COMMIT();

    for (int i = 0; i < 16; i++) {
        if (i + 1 < 16) { issue(i + 1); CP_COMMIT(); CP_WAIT(1); }
        else            { CP_WAIT(0); }
        __syncthreads();

        const uint32_t ab = sb + (uint32_t)(i & 1) * GSTAGE;
        const uint32_t bb = ab + 8192u;

        #pragma unroll
        for (int kst = 0; kst < 4; kst++) {
            const int kk = kst * 16;
            uint32_t a[2][4], b[8][2];
            #pragma unroll
            for (int mt = 0; mt < 2; mt++) {
                int r = warpM * 32 + mt * 16 + (lane & 7) + ((lane >> 3) & 1) * 8;
                int kcol = kk + (lane >> 4) * 8;
                LDSM_X4(a[mt][0], a[mt][1], a[mt][2], a[mt][3],
                        ab + sw128((uint32_t)(r * 128 + kcol * 2)));
            }
            #pragma unroll
            for (int np = 0; np < 4; np++) {
                int r = warpN * 64 + np * 16 + (lane & 7) + (lane >> 4) * 8;
                int kcol = kk + ((lane >> 3) & 1) * 8;
                LDSM_X4(b[2 * np][0], b[2 * np][1], b[2 * np + 1][0], b[2 * np + 1][1],
                        bb + sw128((uint32_t)(r * 128 + kcol * 2)));
            }
            #pragma unroll
            for (int mt = 0; mt < 2; mt++)
                #pragma unroll
                for (int nt = 0; nt < 8; nt++)
                    MMA_F16(c[mt][nt], a[mt], b[nt]);
        }
        __syncthreads();
    }

    #pragma unroll
    for (int mt = 0; mt < 2; mt++) {
        #pragma unroll
        for (int half = 0; half < 2; half++) {
            const int rowg = row0 + warpM * 32 + mt * 16 + (lane >> 2) + half * 8;
            const int bb_ = rowg >> 11, ss = rowg & (S_ - 1);
            #pragma unroll
            for (int nt = 0; nt < 8; nt++) {
                const int colg = col0 + warpN * 64 + nt * 8 + (lane & 3) * 2;
                const float v0 = (c[mt][nt][half * 2 + 0] + bias[colg]) * oscale;
                const float v1 = (c[mt][nt][half * 2 + 1] + bias[colg + 1]) * oscale;
                if (mode < 3) {
                    const int h = colg >> 6;
                    size_t off = ((size_t)((bb_ * H_ + h) * S_ + ss)) * DK_ + (colg & 63);
                    *reinterpret_cast<uint32_t*>(D16 + off) = pack2h(v0, v1);
                } else {
                    *reinterpret_cast<float2*>(Cext + (size_t)rowg * DM_ + colg) =
                        make_float2(v0, v1);
                }
            }
        }
    }
}

__global__ void __launch_bounds__(128, 4) gemm_qkv(const float* __restrict__ bq,
                                                   const float* __restrict__ bk,
                                                   const float* __restrict__ bv)
{
    extern __shared__ __align__(1024) char smem[];
    const int z = blockIdx.z;
    const float* bias = (z == 0) ? bq : (z == 1) ? bk : bv;
    __half* D16 = (z == 0) ? g_Q16 : (z == 1) ? g_K16 : g_V16;
    const float oscale = (z == 0) ? QSCALE : 1.0f;
    gemm_core(g_Ahi[z], g_Whi[z], bias, nullptr, D16, oscale, z, smem);
}

__global__ void __launch_bounds__(128, 4) gemm_out(const float* __restrict__ bo,
                                                   float* __restrict__ out)
{
    extern __shared__ __align__(1024) char smem[];
    gemm_core(g_Ahi[0], g_Whi[3], bo, out, nullptr, 1.0f, 3, smem);
}

// ---------------------------------------------------------------------------
// HMMA flash attention, causal, fp16, log2-domain half2 softmax.
// Bq=64, 64 threads = 2 warps x 32 query rows. Per-fragment QK+softmax
// (re-load K frags per fragment) to cut live registers -> 5 CTAs/SM.
// 2-stage KV ring, depth-1 prefetch, single barrier per tile.
// Wrap-paired schedule. V via ldmatrix.trans. l via ones-MMA.
// Output fp16 into g_Ahi[0] at [B,S,1024].
// ---------------------------------------------------------------------------
#define ATT_SMEM (8192 + 2 * 16384)   // Q 8KB + 2 KV stages = 40 KB

__global__ void __launch_bounds__(64, 5) attn_mma()
{
    extern __shared__ __align__(1024) char smem[];
    const uint32_t sb = smem_u32(smem);
    const int t = threadIdx.x, lane = t & 31, w = t >> 5;   // 2 warps
    const int bh = blockIdx.y;
    const int nqb = (int)(S_ / 64);                         // 32

    const size_t bo = (size_t)bh * S_ * DK_;
    const __half* Qg = g_Q16 + bo;
    const __half* Kg = g_K16 + bo;
    const __half* Vg = g_V16 + bo;
    const uint32_t QB = sb;
    const int b = bh >> 4, h = bh & 15;
    const uint32_t onesf[2] = {0x3C003C00u, 0x3C003C00u};

    #pragma unroll 1
    for (int seg = 0; seg < 2; seg++) {
        const int qb = seg ? (int)blockIdx.x : (nqb - 1 - (int)blockIdx.x);
        const int qs = qb * 64;
        const int nt = qb + 1;

        if (seg) __syncthreads();

        auto issueKV = [&](int i) {
            const int kt = i * 64;
            const uint32_t bB = sb + 8192u + (uint32_t)(i & 1) * 16384u;
            #pragma unroll
            for (int j = 0; j < 8; j++) {
                int g = t + j * 64, r = g >> 3, c = (g & 7) * 8;
                uint32_t so = sw128((uint32_t)(r * 128 + c * 2));
                CP_ASYNC16(bB + so,        Kg + (size_t)(kt + r) * DK_ + c);
                CP_ASYNC16(bB + 8192 + so, Vg + (size_t)(kt + r) * DK_ + c);
            }
        };
        // prologue: Q tile + KV0 in one group
        #pragma unroll
        for (int j = 0; j < 8; j++) {
            int g = t + j * 64, r = g >> 3, c = (g & 7) * 8;
            uint32_t so = sw128((uint32_t)(r * 128 + c * 2));
            CP_ASYNC16(QB + so, Qg + (size_t)(qs + r) * DK_ + c);
        }
        issueKV(0);
        CP_COMMIT();

        uint32_t qf[2][4][4];
        float o[2][8][4] = {};
        float ol[2][4] = {};
        float mrow[2][2] = {{-INFINITY, -INFINITY}, {-INFINITY, -INFINITY}};

        for (int i = 0; i < nt; i++) {
            CP_WAIT(0);                 // tile i (and Q on i==0) resident
            __syncthreads();
            if (i + 1 < nt) { issueKV(i + 1); CP_COMMIT(); }   // depth-1 prefetch

            if (i == 0) {
                #pragma unroll
                for (int f = 0; f < 2; f++)
                    #pragma unroll
                    for (int kc = 0; kc < 4; kc++) {
                        int r = w * 32 + f * 16 + (lane & 7) + ((lane >> 3) & 1) * 8;
                        int kcol = kc * 16 + (lane >> 4) * 8;
                        LDSM_X4(qf[f][kc][0], qf[f][kc][1], qf[f][kc][2], qf[f][kc][3],
                                QB + sw128((uint32_t)(r * 128 + kcol * 2)));
                    }
            }

            const int kt = i * 64;
            const uint32_t bB = sb + 8192u + (uint32_t)(i & 1) * 16384u;

            // ---- per-fragment: S = Q K^T, mask, softmax -> pf[f]
            uint32_t pf[2][4][4];
            #pragma unroll
            for (int f = 0; f < 2; f++) {
                float s[8][4] = {};
                #pragma unroll
                for (int kc = 0; kc < 4; kc++) {
                    const int kk = kc * 16;
                    uint32_t bf[8][2];
                    #pragma unroll
                    for (int np = 0; np < 4; np++) {
                        int r = np * 16 + (lane & 7) + (lane >> 4) * 8;
                        int kcol = kk + ((lane >> 3) & 1) * 8;
                        LDSM_X4(bf[2 * np][0], bf[2 * np][1], bf[2 * np + 1][0], bf[2 * np + 1][1],
                                bB + sw128((uint32_t)(r * 128 + kcol * 2)));
                    }
                    #pragma unroll
                    for (int j = 0; j < 8; j++)
                        MMA_F16(s[j], qf[f][kc], bf[j]);
                }

                const int rbase = qs + w * 32 + f * 16;
                const int r0g = rbase + (lane >> 2);
                if (kt + 63 > rbase) {
                    #pragma unroll
                    for (int j = 0; j < 8; j++) {
                        const int cg = kt + j * 8 + (lane & 3) * 2;
                        if (cg     > r0g)     s[j][0] = -INFINITY;
                        if (cg + 1 > r0g)     s[j][1] = -INFINITY;
                        if (cg     > r0g + 8) s[j][2] = -INFINITY;
                        if (cg + 1 > r0g + 8) s[j][3] = -INFINITY;
                    }
                }
                __half2 hp0[8], hp1[8];
                #pragma unroll
                for (int j = 0; j < 8; j++) {
                    hp0[j] = __floats2half2_rn(s[j][0], s[j][1]);
                    hp1[j] = __floats2half2_rn(s[j][2], s[j][3]);
                }
                __half2 hm0 = hp0[0], hm1 = hp1[0];
                #pragma unroll
                for (int j = 1; j < 8; j++) {
                    hm0 = __hmax2(hm0, hp0[j]);
                    hm1 = __hmax2(hm1, hp1[j]);
                }
                float mx0 = fmaxf(__low2float(hm0), __high2float(hm0));
                float mx1 = fmaxf(__low2float(hm1), __high2float(hm1));
                mx0 = fmaxf(mx0, __shfl_xor_sync(0xffffffffu, mx0, 1));
                mx0 = fmaxf(mx0, __shfl_xor_sync(0xffffffffu, mx0, 2));
                mx1 = fmaxf(mx1, __shfl_xor_sync(0xffffffffu, mx1, 1));
                mx1 = fmaxf(mx1, __shfl_xor_sync(0xffffffffu, mx1, 2));
                const float mn0 = fmaxf(mrow[f][0], mx0), mn1 = fmaxf(mrow[f][1], mx1);
                const float al0 = ex2f(mrow[f][0] - mn0), al1 = ex2f(mrow[f][1] - mn1);
                mrow[f][0] = mn0; mrow[f][1] = mn1;

                const __half2 mn0h = __float2half2_rn(mn0);
                const __half2 mn1h = __float2half2_rn(mn1);
                #pragma unroll
                for (int kc = 0; kc < 4; kc++) {
                    pf[f][kc][0] = ex2h2(__hsub2(hp0[2 * kc],     mn0h));
                    pf[f][kc][1] = ex2h2(__hsub2(hp1[2 * kc],     mn1h));
                    pf[f][kc][2] = ex2h2(__hsub2(hp0[2 * kc + 1], mn0h));
                    pf[f][kc][3] = ex2h2(__hsub2(hp1[2 * kc + 1], mn1h));
                }

                if (!(al0 == 1.0f && al1 == 1.0f)) {
                    #pragma unroll
                    for (int j = 0; j < 8; j++) {
                        o[f][j][0] *= al0; o[f][j][1] *= al0;
                        o[f][j][2] *= al1; o[f][j][3] *= al1;
                    }
                    ol[f][0] *= al0; ol[f][1] *= al0;
                    ol[f][2] *= al1; ol[f][3] *= al1;
                }
            }

            // ---- O += P V (shared vf across fragments); l += P·1
            #pragma unroll
            for (int kc = 0; kc < 4; kc++) {
                const int kk = kc * 16;
                uint32_t vf[8][2];
                #pragma unroll
                for (int np = 0; np < 4; np++) {
                    int r = kk + (lane & 7) + ((lane >> 3) & 1) * 8;
                    int dcol = np * 16 + (lane >> 4) * 8;
                    LDSM_X4_T(vf[2 * np][0], vf[2 * np][1], vf[2 * np + 1][0], vf[2 * np + 1][1],
                              bB + 8192 + sw128((uint32_t)(r * 128 + dcol * 2)));
                }
                #pragma unroll
                for (int f = 0; f < 2; f++) {
                    #pragma unroll
                    for (int j = 0; j < 8; j++)
                        MMA_F16(o[f][j], pf[f][kc], vf[j]);
                    MMA_F16(ol[f], pf[f][kc], onesf);
                }
            }
        }

        // ---- epilogue: normalize, write fp16 to [B,S,1024]
        #pragma unroll
        for (int f = 0; f < 2; f++) {
            const float inv0 = 1.0f / ol[f][0], inv1 = 1.0f / ol[f][2];
            const int row0g = qs + w * 32 + f * 16 + (lane >> 2);
            #pragma unroll
            for (int j = 0; j < 8; j++) {
                const int d = j * 8 + (lane & 3) * 2;
                size_t off0 = (size_t)(b * S_ + row0g) * DM_ + h * DK_ + d;
                size_t off1 = off0 + (size_t)8 * DM_;
                *reinterpret_cast<uint32_t*>(g_Ahi[0] + off0) =
                    pack2h(o[f][j][0] * inv0, o[f][j][1] * inv0);
                *reinterpret_cast<uint32_t*>(g_Ahi[0] + off1) =
                    pack2h(o[f][j][2] * inv1, o[f][j][3] * inv1);
            }
        }
    }
}

// ----------------------------------------------------------------------------
extern "C" void kernel_launch(void* const* d_in, const int* in_sizes, int n_in,
                              void* d_out, int out_size)
{
    const float* query = (const float*)d_in[0];
    const float* key   = (const float*)d_in[1];
    const float* value = (const float*)d_in[2];
    const float* Wq = (const float*)d_in[4];
    const float* bq = (const float*)d_in[5];
    const float* Wk = (const float*)d_in[6];
    const float* bk = (const float*)d_in[7];
    const float* Wv = (const float*)d_in[8];
    const float* bv = (const float*)d_in[9];
    const float* Wo = (const float*)d_in[10];
    const float* bo = (const float*)d_in[11];
    float* out = (float*)d_out;

    cudaFuncSetAttribute(gemm_qkv, cudaFuncAttributeMaxDynamicSharedMemorySize, GEMM_SMEM);
    cudaFuncSetAttribute(gemm_out, cudaFuncAttributeMaxDynamicSharedMemorySize, GEMM_SMEM);
    cudaFuncSetAttribute(attn_mma, cudaFuncAttributeMaxDynamicSharedMemorySize, ATT_SMEM);

    const int n4 = M_ * DM_ / 4;

    conv_inputs<<<dim3(n4 / 256, 3), 256>>>((const float4*)query, (const float4*)key,
                                            (const float4*)value);
    conv_weights<<<dim3(32, 32, 4), dim3(32, 8)>>>(Wq, Wk, Wv, Wo);

    gemm_qkv<<<dim3(DM_ / GN, M_ / GM, 3), 128, GEMM_SMEM>>>(bq, bk, bv);
    attn_mma<<<dim3(S_ / 128, B_ * H_), 64, ATT_SMEM>>>();
    gemm_out<<<dim3(DM_ / GN, M_ / GM), 128, GEMM_SMEM>>>(bo, out);
}

// round 17
// speedup vs baseline: 1.0996x; 1.0996x over previous
#include <cuda_runtime.h>
#include <cuda_fp16.h>
#include <math.h>
#include <cstdint>

#define B_   2
#define S_   2048
#define H_   16
#define DK_  64
#define DM_  1024
#define M_   (B_ * S_)   // 4096

// ---------------------------------------------------------------------------
// PTX helpers — sm_80+ portable (harness PTX target is sm_103 WITHOUT 'a';
// tcgen05/TMEM unavailable; mma.sync/ldmatrix/cp.async are the path).
// ---------------------------------------------------------------------------
__device__ __forceinline__ uint32_t smem_u32(const void* p) {
    uint32_t a;
    asm("{ .reg .u64 t; cvta.to.shared.u64 t, %1; cvt.u32.u64 %0, t; }" : "=r"(a) : "l"(p));
    return a;
}
#define CP_ASYNC16(dst, src) \
    asm volatile("cp.async.cg.shared.global [%0], [%1], 16;" :: "r"(dst), "l"(src))
#define CP_COMMIT() asm volatile("cp.async.commit_group;" ::: "memory")
#define CP_WAIT(n)  asm volatile("cp.async.wait_group %0;" :: "n"(n) : "memory")

#define LDSM_X4(r0, r1, r2, r3, addr) \
    asm volatile("ldmatrix.sync.aligned.m8n8.x4.shared.b16 {%0,%1,%2,%3}, [%4];" \
                 : "=r"(r0), "=r"(r1), "=r"(r2), "=r"(r3) : "r"(addr))

#define LDSM_X4_T(r0, r1, r2, r3, addr) \
    asm volatile("ldmatrix.sync.aligned.m8n8.x4.trans.shared.b16 {%0,%1,%2,%3}, [%4];" \
                 : "=r"(r0), "=r"(r1), "=r"(r2), "=r"(r3) : "r"(addr))

#define MMA_F16(c, a, b) \
    asm volatile("mma.sync.aligned.m16n8k16.row.col.f32.f16.f16.f32 " \
                 "{%0,%1,%2,%3}, {%4,%5,%6,%7}, {%8,%9}, {%0,%1,%2,%3};" \
                 : "+f"((c)[0]), "+f"((c)[1]), "+f"((c)[2]), "+f"((c)[3]) \
                 : "r"((a)[0]), "r"((a)[1]), "r"((a)[2]), "r"((a)[3]), \
                   "r"((b)[0]), "r"((b)[1]))

__device__ __forceinline__ uint32_t sw128(uint32_t off) { return off ^ ((off >> 3) & 0x70); }

__device__ __forceinline__ uint32_t pack2h(float x, float y) {
    __half2 h2 = __halves2half2(__float2half(x), __float2half(y));
    return *reinterpret_cast<uint32_t*>(&h2);
}
__device__ __forceinline__ float ex2f(float x) {
    float r;
    asm("ex2.approx.f32 %0, %1;" : "=f"(r) : "f"(x));
    return r;
}
__device__ __forceinline__ uint32_t ex2h2(__half2 x) {
    uint32_t xi = *reinterpret_cast<uint32_t*>(&x), r;
    asm("ex2.approx.f16x2 %0, %1;" : "=r"(r) : "r"(xi));
    return r;
}

// Q prescale: 1/sqrt(64) * log2(e)  (softmax runs in log2 domain)
#define QSCALE 0.18033688011112042f

// ---------------------------------------------------------------------------
// Scratch (device globals)
// ---------------------------------------------------------------------------
__device__ __half g_Ahi[3][(size_t)M_ * DM_];    // A operands (0 reused for attn out)
__device__ __half g_Whi[4][(size_t)DM_ * DM_];   // W^T [N,K] K-contig
__device__ __half g_Q16[B_ * H_ * S_ * DK_];     // [B,H,S,64], pre-scaled by QSCALE
__device__ __half g_K16[B_ * H_ * S_ * DK_];
__device__ __half g_V16[B_ * H_ * S_ * DK_];

// ---------------------------------------------------------------------------
// Combined conversions: z in [0,3) -> input fp32->fp16; z in [3,7) -> weight
// transpose fp32->fp16. Excess blocks exit early.
// ---------------------------------------------------------------------------
__global__ void __launch_bounds__(256) conv_all(const float4* __restrict__ s0,
                                                const float4* __restrict__ s1,
                                                const float4* __restrict__ s2,
                                                const float* __restrict__ W0,
                                                const float* __restrict__ W1,
                                                const float* __restrict__ W2,
                                                const float* __restrict__ W3)
{
    const int z = blockIdx.y;
    if (z < 3) {
        const float4* src = (z == 0) ? s0 : (z == 1) ? s1 : s2;
        uint32_t* hi = reinterpret_cast<uint32_t*>(g_Ahi[z]);
        int i = blockIdx.x * 256 + threadIdx.x;
        float4 v = src[i];
        hi[2 * i + 0] = pack2h(v.x, v.y);
        hi[2 * i + 1] = pack2h(v.z, v.w);
    } else {
        if (blockIdx.x >= 1024) return;
        __shared__ float tile[32][33];
        const int which = z - 3;
        const float* W = (which == 0) ? W0 : (which == 1) ? W1 : (which == 2) ? W2 : W3;
        __half* hi = g_Whi[which];
        const int bx = blockIdx.x & 31, by = blockIdx.x >> 5;
        const int tx = threadIdx.x & 31, ty = threadIdx.x >> 5;   // 32 x 8
        #pragma unroll
        for (int j = 0; j < 32; j += 8)
            tile[ty + j][tx] = W[(size_t)(by * 32 + ty + j) * DM_ + bx * 32 + tx];
        __syncthreads();
        #pragma unroll
        for (int j = 0; j < 32; j += 8)
            hi[(size_t)(bx * 32 + ty + j) * DM_ + by * 32 + tx] = __float2half(tile[tx][ty + j]);
    }
}

// ---------------------------------------------------------------------------
// Single-pass HMMA GEMM core: 64x128 CTA tile, 128 threads (2Mx2N warps,
// warp tile 32x64), BK=64, 2-stage cp.async, 4 CTAs/SM. (unchanged R14/R15)
// ---------------------------------------------------------------------------
#define GM 64
#define GN 128
#define GSTAGE 24576
#define GEMM_SMEM (2 * GSTAGE)

__device__ __forceinline__ void gemm_core(const __half* __restrict__ A,
                                          const __half* __restrict__ W,
                                          const float* __restrict__ bias,
                                          float* __restrict__ Cext,
                                          __half* __restrict__ D16,
                                          float oscale, int mode, char* smem)
{
    const uint32_t sb = smem_u32(smem);
    const int t = threadIdx.x, lane = t & 31, wid = t >> 5;
    const int warpM = wid >> 1, warpN = wid & 1;
    const int row0 = blockIdx.y * GM, col0 = blockIdx.x * GN;

    float c[2][8][4] = {};

    auto issue = [&](int i) {
        const int kc = i * 64;
        const uint32_t ab = sb + (uint32_t)(i & 1) * GSTAGE;
        const uint32_t bb = ab + 8192u;
        #pragma unroll
        for (int j = 0; j < 4; j++) {
            int g = t + j * 128, r = g >> 3, ccol = (g & 7) * 8;
            uint32_t so = sw128((uint32_t)(r * 128 + ccol * 2));
            CP_ASYNC16(ab + so, A + (size_t)(row0 + r) * DM_ + kc + ccol);
        }
        #pragma unroll
        for (int j = 0; j < 8; j++) {
            int g = t + j * 128, r = g >> 3, ccol = (g & 7) * 8;
            uint32_t so = sw128((uint32_t)(r * 128 + ccol * 2));
            CP_ASYNC16(bb + so, W + (size_t)(col0 + r) * DM_ + kc + ccol);
        }
    };

    issue(0);
    CP_COMMIT();

    for (int i = 0; i < 16; i++) {
        if (i + 1 < 16) { issue(i + 1); CP_COMMIT(); CP_WAIT(1); }
        else            { CP_WAIT(0); }
        __syncthreads();

        const uint32_t ab = sb + (uint32_t)(i & 1) * GSTAGE;
        const uint32_t bb = ab + 8192u;

        #pragma unroll
        for (int kst = 0; kst < 4; kst++) {
            const int kk = kst * 16;
            uint32_t a[2][4], b[8][2];
            #pragma unroll
            for (int mt = 0; mt < 2; mt++) {
                int r = warpM * 32 + mt * 16 + (lane & 7) + ((lane >> 3) & 1) * 8;
                int kcol = kk + (lane >> 4) * 8;
                LDSM_X4(a[mt][0], a[mt][1], a[mt][2], a[mt][3],
                        ab + sw128((uint32_t)(r * 128 + kcol * 2)));
            }
            #pragma unroll
            for (int np = 0; np < 4; np++) {
                int r = warpN * 64 + np * 16 + (lane & 7) + (lane >> 4) * 8;
                int kcol = kk + ((lane >> 3) & 1) * 8;
                LDSM_X4(b[2 * np][0], b[2 * np][1], b[2 * np + 1][0], b[2 * np + 1][1],
                        bb + sw128((uint32_t)(r * 128 + kcol * 2)));
            }
            #pragma unroll
            for (int mt = 0; mt < 2; mt++)
                #pragma unroll
                for (int nt = 0; nt < 8; nt++)
                    MMA_F16(c[mt][nt], a[mt], b[nt]);
        }
        __syncthreads();
    }

    #pragma unroll
    for (int mt = 0; mt < 2; mt++) {
        #pragma unroll
        for (int half = 0; half < 2; half++) {
            const int rowg = row0 + warpM * 32 + mt * 16 + (lane >> 2) + half * 8;
            const int bb_ = rowg >> 11, ss = rowg & (S_ - 1);
            #pragma unroll
            for (int nt = 0; nt < 8; nt++) {
                const int colg = col0 + warpN * 64 + nt * 8 + (lane & 3) * 2;
                const float v0 = (c[mt][nt][half * 2 + 0] + bias[colg]) * oscale;
                const float v1 = (c[mt][nt][half * 2 + 1] + bias[colg + 1]) * oscale;
                if (mode < 3) {
                    const int h = colg >> 6;
                    size_t off = ((size_t)((bb_ * H_ + h) * S_ + ss)) * DK_ + (colg & 63);
                    *reinterpret_cast<uint32_t*>(D16 + off) = pack2h(v0, v1);
                } else {
                    *reinterpret_cast<float2*>(Cext + (size_t)rowg * DM_ + colg) =
                        make_float2(v0, v1);
                }
            }
        }
    }
}

__global__ void __launch_bounds__(128, 4) gemm_qkv(const float* __restrict__ bq,
                                                   const float* __restrict__ bk,
                                                   const float* __restrict__ bv)
{
    extern __shared__ __align__(1024) char smem[];
    const int z = blockIdx.z;
    const float* bias = (z == 0) ? bq : (z == 1) ? bk : bv;
    __half* D16 = (z == 0) ? g_Q16 : (z == 1) ? g_K16 : g_V16;
    const float oscale = (z == 0) ? QSCALE : 1.0f;
    gemm_core(g_Ahi[z], g_Whi[z], bias, nullptr, D16, oscale, z, smem);
}

__global__ void __launch_bounds__(128, 4) gemm_out(const float* __restrict__ bo,
                                                   float* __restrict__ out)
{
    extern __shared__ __align__(1024) char smem[];
    gemm_core(g_Ahi[0], g_Whi[3], bo, out, nullptr, 1.0f, 3, smem);
}

// ---------------------------------------------------------------------------
// HMMA flash attention (exact R15 config — best measured): causal, fp16,
// log2-domain half2 softmax. Bq=64, 64 threads = 2 warps x 32 query rows,
// joint QK (shared bf frags), 3-stage KV ring, wrap-paired schedule,
// V via ldmatrix.trans, l via ones-MMA. Output fp16 into g_Ahi[0].
// ---------------------------------------------------------------------------
#define ATT_SMEM (8192 + 3 * 16384)   // 56 KB

__global__ void __launch_bounds__(64, 4) attn_mma()
{
    extern __shared__ __align__(1024) char smem[];
    const uint32_t sb = smem_u32(smem);
    const int t = threadIdx.x, lane = t & 31, w = t >> 5;   // 2 warps
    const int bh = blockIdx.y;
    const int nqb = (int)(S_ / 64);                         // 32

    const size_t bo = (size_t)bh * S_ * DK_;
    const __half* Qg = g_Q16 + bo;
    const __half* Kg = g_K16 + bo;
    const __half* Vg = g_V16 + bo;
    const uint32_t QB = sb;
    const int b = bh >> 4, h = bh & 15;
    const uint32_t onesf[2] = {0x3C003C00u, 0x3C003C00u};

    #pragma unroll 1
    for (int seg = 0; seg < 2; seg++) {
        const int qb = seg ? (int)blockIdx.x : (nqb - 1 - (int)blockIdx.x);
        const int qs = qb * 64;
        const int nt = qb + 1;

        if (seg) __syncthreads();

        #pragma unroll
        for (int j = 0; j < 8; j++) {
            int g = t + j * 64, r = g >> 3, c = (g & 7) * 8;
            uint32_t so = sw128((uint32_t)(r * 128 + c * 2));
            CP_ASYNC16(QB + so, Qg + (size_t)(qs + r) * DK_ + c);
        }
        auto issueKV = [&](int i) {
            const int kt = i * 64;
            const uint32_t bB = sb + 8192u + (uint32_t)(i % 3) * 16384u;
            #pragma unroll
            for (int j = 0; j < 8; j++) {
                int g = t + j * 64, r = g >> 3, c = (g & 7) * 8;
                uint32_t so = sw128((uint32_t)(r * 128 + c * 2));
                CP_ASYNC16(bB + so,        Kg + (size_t)(kt + r) * DK_ + c);
                CP_ASYNC16(bB + 8192 + so, Vg + (size_t)(kt + r) * DK_ + c);
            }
        };
        issueKV(0);
        CP_COMMIT();
        if (nt > 1) { issueKV(1); CP_COMMIT(); }

        uint32_t qf[2][4][4];                  // 2 m16 fragments x 4 kc
        float o[2][8][4] = {};
        float ol[2][4] = {};
        float mrow[2][2] = {{-INFINITY, -INFINITY}, {-INFINITY, -INFINITY}};

        for (int i = 0; i < nt; i++) {
            if (i + 1 < nt) CP_WAIT(1); else CP_WAIT(0);
            __syncthreads();
            if (i + 2 < nt) { issueKV(i + 2); CP_COMMIT(); }

            if (i == 0) {
                #pragma unroll
                for (int f = 0; f < 2; f++)
                    #pragma unroll
                    for (int kc = 0; kc < 4; kc++) {
                        int r = w * 32 + f * 16 + (lane & 7) + ((lane >> 3) & 1) * 8;
                        int kcol = kc * 16 + (lane >> 4) * 8;
                        LDSM_X4(qf[f][kc][0], qf[f][kc][1], qf[f][kc][2], qf[f][kc][3],
                                QB + sw128((uint32_t)(r * 128 + kcol * 2)));
                    }
            }

            const int kt = i * 64;
            const uint32_t bB = sb + 8192u + (uint32_t)(i % 3) * 16384u;

            // ---- S = Q K^T (log2 domain), shared bf across both fragments
            float s[2][8][4] = {};
            #pragma unroll
            for (int kc = 0; kc < 4; kc++) {
                const int kk = kc * 16;
                uint32_t bf[8][2];
                #pragma unroll
                for (int np = 0; np < 4; np++) {
                    int r = np * 16 + (lane & 7) + (lane >> 4) * 8;
                    int kcol = kk + ((lane >> 3) & 1) * 8;
                    LDSM_X4(bf[2 * np][0], bf[2 * np][1], bf[2 * np + 1][0], bf[2 * np + 1][1],
                            bB + sw128((uint32_t)(r * 128 + kcol * 2)));
                }
                #pragma unroll
                for (int f = 0; f < 2; f++)
                    #pragma unroll
                    for (int j = 0; j < 8; j++)
                        MMA_F16(s[f][j], qf[f][kc], bf[j]);
            }

            // ---- per-fragment softmax -> pf
            uint32_t pf[2][4][4];
            #pragma unroll
            for (int f = 0; f < 2; f++) {
                const int rbase = qs + w * 32 + f * 16;
                const int r0g = rbase + (lane >> 2);
                if (kt + 63 > rbase) {
                    #pragma unroll
                    for (int j = 0; j < 8; j++) {
                        const int cg = kt + j * 8 + (lane & 3) * 2;
                        if (cg     > r0g)     s[f][j][0] = -INFINITY;
                        if (cg + 1 > r0g)     s[f][j][1] = -INFINITY;
                        if (cg     > r0g + 8) s[f][j][2] = -INFINITY;
                        if (cg + 1 > r0g + 8) s[f][j][3] = -INFINITY;
                    }
                }
                __half2 hp0[8], hp1[8];
                #pragma unroll
                for (int j = 0; j < 8; j++) {
                    hp0[j] = __floats2half2_rn(s[f][j][0], s[f][j][1]);
                    hp1[j] = __floats2half2_rn(s[f][j][2], s[f][j][3]);
                }
                __half2 hm0 = hp0[0], hm1 = hp1[0];
                #pragma unroll
                for (int j = 1; j < 8; j++) {
                    hm0 = __hmax2(hm0, hp0[j]);
                    hm1 = __hmax2(hm1, hp1[j]);
                }
                float mx0 = fmaxf(__low2float(hm0), __high2float(hm0));
                float mx1 = fmaxf(__low2float(hm1), __high2float(hm1));
                mx0 = fmaxf(mx0, __shfl_xor_sync(0xffffffffu, mx0, 1));
                mx0 = fmaxf(mx0, __shfl_xor_sync(0xffffffffu, mx0, 2));
                mx1 = fmaxf(mx1, __shfl_xor_sync(0xffffffffu, mx1, 1));
                mx1 = fmaxf(mx1, __shfl_xor_sync(0xffffffffu, mx1, 2));
                const float mn0 = fmaxf(mrow[f][0], mx0), mn1 = fmaxf(mrow[f][1], mx1);
                const float al0 = ex2f(mrow[f][0] - mn0), al1 = ex2f(mrow[f][1] - mn1);
                mrow[f][0] = mn0; mrow[f][1] = mn1;

                const __half2 mn0h = __float2half2_rn(mn0);
                const __half2 mn1h = __float2half2_rn(mn1);
                #pragma unroll
                for (int kc = 0; kc < 4; kc++) {
                    pf[f][kc][0] = ex2h2(__hsub2(hp0[2 * kc],     mn0h));
                    pf[f][kc][1] = ex2h2(__hsub2(hp1[2 * kc],     mn1h));
                    pf[f][kc][2] = ex2h2(__hsub2(hp0[2 * kc + 1], mn0h));
                    pf[f][kc][3] = ex2h2(__hsub2(hp1[2 * kc + 1], mn1h));
                }

                if (!(al0 == 1.0f && al1 == 1.0f)) {
                    #pragma unroll
                    for (int j = 0; j < 8; j++) {
                        o[f][j][0] *= al0; o[f][j][1] *= al0;
                        o[f][j][2] *= al1; o[f][j][3] *= al1;
                    }
                    ol[f][0] *= al0;            // only [0]/[2] are read
                    ol[f][2] *= al1;
                }
            }

            // ---- O += P V (shared vf across fragments); l += P·1
            #pragma unroll
            for (int kc = 0; kc < 4; kc++) {
                const int kk = kc * 16;
                uint32_t vf[8][2];
                #pragma unroll
                for (int np = 0; np < 4; np++) {
                    int r = kk + (lane & 7) + ((lane >> 3) & 1) * 8;
                    int dcol = np * 16 + (lane >> 4) * 8;
                    LDSM_X4_T(vf[2 * np][0], vf[2 * np][1], vf[2 * np + 1][0], vf[2 * np + 1][1],
                              bB + 8192 + sw128((uint32_t)(r * 128 + dcol * 2)));
                }
                #pragma unroll
                for (int f = 0; f < 2; f++) {
                    #pragma unroll
                    for (int j = 0; j < 8; j++)
                        MMA_F16(o[f][j], pf[f][kc], vf[j]);
                    MMA_F16(ol[f], pf[f][kc], onesf);
                }
            }
        }

        // ---- epilogue: normalize, write fp16 to [B,S,1024]
        #pragma unroll
        for (int f = 0; f < 2; f++) {
            const float inv0 = 1.0f / ol[f][0], inv1 = 1.0f / ol[f][2];
            const int row0g = qs + w * 32 + f * 16 + (lane >> 2);
            #pragma unroll
            for (int j = 0; j < 8; j++) {
                const int d = j * 8 + (lane & 3) * 2;
                size_t off0 = (size_t)(b * S_ + row0g) * DM_ + h * DK_ + d;
                size_t off1 = off0 + (size_t)8 * DM_;
                *reinterpret_cast<uint32_t*>(g_Ahi[0] + off0) =
                    pack2h(o[f][j][0] * inv0, o[f][j][1] * inv0);
                *reinterpret_cast<uint32_t*>(g_Ahi[0] + off1) =
                    pack2h(o[f][j][2] * inv1, o[f][j][3] * inv1);
            }
        }
    }
}

// ----------------------------------------------------------------------------
extern "C" void kernel_launch(void* const* d_in, const int* in_sizes, int n_in,
                              void* d_out, int out_size)
{
    const float* query = (const float*)d_in[0];
    const float* key   = (const float*)d_in[1];
    const float* value = (const float*)d_in[2];
    const float* Wq = (const float*)d_in[4];
    const float* bq = (const float*)d_in[5];
    const float* Wk = (const float*)d_in[6];
    const float* bk = (const float*)d_in[7];
    const float* Wv = (const float*)d_in[8];
    const float* bv = (const float*)d_in[9];
    const float* Wo = (const float*)d_in[10];
    const float* bo = (const float*)d_in[11];
    float* out = (float*)d_out;

    cudaFuncSetAttribute(gemm_qkv, cudaFuncAttributeMaxDynamicSharedMemorySize, GEMM_SMEM);
    cudaFuncSetAttribute(gemm_out, cudaFuncAttributeMaxDynamicSharedMemorySize, GEMM_SMEM);
    cudaFuncSetAttribute(attn_mma, cudaFuncAttributeMaxDynamicSharedMemorySize, ATT_SMEM);

    const int n4 = M_ * DM_ / 4;

    conv_all<<<dim3(n4 / 256, 7), 256>>>((const float4*)query, (const float4*)key,
                                         (const float4*)value, Wq, Wk, Wv, Wo);

    gemm_qkv<<<dim3(DM_ / GN, M_ / GM, 3), 128, GEMM_SMEM>>>(bq, bk, bv);
    attn_mma<<<dim3(S_ / 128, B_ * H_), 64, ATT_SMEM>>>();
    gemm_out<<<dim3(DM_ / GN, M_ / GM), 128, GEMM_SMEM>>>(bo, out);
}